// round 3
// baseline (speedup 1.0000x reference)
#include <cuda_runtime.h>
#include <cstdint>

#define IMG_H 1024
#define IMG_W 1024
#define EPS_F 1e-6f
#define BG_WF 1e-4f

// Scratch accumulator: per pixel {w*f0, w*f1, w*f2, w}. 16 MB, L2-resident.
__device__ float4 g_accum[IMG_H * IMG_W];

__global__ __launch_bounds__(256) void clear_kernel() {
    int i = blockIdx.x * blockDim.x + threadIdx.x;
    if (i < IMG_H * IMG_W) g_accum[i] = make_float4(0.f, 0.f, 0.f, 0.f);
}

__global__ __launch_bounds__(256) void scatter_kernel(
    const float* __restrict__ cam,
    const float* __restrict__ pts,
    int n)
{
    int i = blockIdx.x * blockDim.x + threadIdx.x;
    if (i >= n) return;

    // Camera (uniform broadcast loads)
    float R00 = __ldg(cam + 0),  R01 = __ldg(cam + 1),  R02 = __ldg(cam + 2),  t0 = __ldg(cam + 3);
    float R10 = __ldg(cam + 4),  R11 = __ldg(cam + 5),  R12 = __ldg(cam + 6),  t1 = __ldg(cam + 7);
    float R20 = __ldg(cam + 8),  R21 = __ldg(cam + 9),  R22 = __ldg(cam + 10), t2 = __ldg(cam + 11);
    float fx  = __ldg(cam + 12), fy  = __ldg(cam + 13), cx  = __ldg(cam + 14), cy = __ldg(cam + 15);

    // Point row: [x, y, z, f0, f1, f2]; byte offset 24*i is 8-aligned.
    const float2* p2 = reinterpret_cast<const float2*>(pts + (size_t)i * 6);
    float2 a = p2[0];   // x, y
    float2 b = p2[1];   // z, f0
    float2 c = p2[2];   // f1, f2

    float px = a.x, py = a.y, pz = b.x;
    float f0 = b.y, f1 = c.x, f2 = c.y;

    // Reference-identical rounding: each multiply/add rounded separately
    // (no FMA contraction — floor(u) boundary decisions must match XLA).
    float xc = __fadd_rn(__fadd_rn(__fadd_rn(__fmul_rn(px, R00), __fmul_rn(py, R01)), __fmul_rn(pz, R02)), t0);
    float yc = __fadd_rn(__fadd_rn(__fadd_rn(__fmul_rn(px, R10), __fmul_rn(py, R11)), __fmul_rn(pz, R12)), t1);
    float zc = __fadd_rn(__fadd_rn(__fadd_rn(__fmul_rn(px, R20), __fmul_rn(py, R21)), __fmul_rn(pz, R22)), t2);

    float inv_z = __fdiv_rn(1.0f, fmaxf(zc, EPS_F));
    float u = __fadd_rn(__fmul_rn(__fmul_rn(fx, xc), inv_z), cx);
    float v = __fadd_rn(__fmul_rn(__fmul_rn(fy, yc), inv_z), cy);
    int ui = (int)floorf(u);
    int vi = (int)floorf(v);

    if (zc > EPS_F && ui >= 0 && ui < IMG_W && vi >= 0 && vi < IMG_H) {
        float w = inv_z;
        float4* dst = &g_accum[vi * IMG_W + ui];
        asm volatile("red.global.add.v4.f32 [%0], {%1, %2, %3, %4};"
                     :: "l"(dst),
                        "f"(__fmul_rn(w, f0)),
                        "f"(__fmul_rn(w, f1)),
                        "f"(__fmul_rn(w, f2)),
                        "f"(w)
                     : "memory");
    }
}

__global__ __launch_bounds__(256) void normalize_kernel(
    const float* __restrict__ env,
    float* __restrict__ out)
{
    int i = blockIdx.x * blockDim.x + threadIdx.x;
    if (i >= IMG_H * IMG_W) return;
    float4 acc = g_accum[i];
    float inv = __fdiv_rn(1.0f, __fadd_rn(acc.w, BG_WF));
    float e0 = env[3 * i + 0];
    float e1 = env[3 * i + 1];
    float e2 = env[3 * i + 2];
    out[3 * i + 0] = __fmul_rn(__fadd_rn(acc.x, __fmul_rn(BG_WF, e0)), inv);
    out[3 * i + 1] = __fmul_rn(__fadd_rn(acc.y, __fmul_rn(BG_WF, e1)), inv);
    out[3 * i + 2] = __fmul_rn(__fadd_rn(acc.z, __fmul_rn(BG_WF, e2)), inv);
}

extern "C" void kernel_launch(void* const* d_in, const int* in_sizes, int n_in,
                              void* d_out, int out_size)
{
    // Inputs: cam_type (int32), camera (16 f32), points (N*6 f32), environment (H*W*3 f32).
    const float* camera = (const float*)d_in[1];
    const float* points = (const float*)d_in[2];
    const float* env    = (const float*)d_in[3];
    float* out = (float*)d_out;
    int n = in_sizes[2] / 6;

    const int T = 256;
    clear_kernel<<<(IMG_H * IMG_W + T - 1) / T, T>>>();
    scatter_kernel<<<(n + T - 1) / T, T>>>(camera, points, n);
    normalize_kernel<<<(IMG_H * IMG_W + T - 1) / T, T>>>(env, out);
}

// round 6
// speedup vs baseline: 1.0508x; 1.0508x over previous
#include <cuda_runtime.h>
#include <cstdint>

#define IMG_H 1024
#define IMG_W 1024
#define NPIX (IMG_H * IMG_W)
#define EPS_F 1e-6f
#define BG_WF 1e-4f

// Scratch accumulator: per pixel {w*f0, w*f1, w*f2, w}. 16 MB, L2-resident.
// Zero-initialized at module load; normalize_kernel re-zeroes it after reading,
// so every kernel_launch invocation sees a zeroed accumulator (no clear kernel).
__device__ float4 g_accum[NPIX];

__global__ __launch_bounds__(256) void scatter_kernel(
    const float* __restrict__ cam,
    const float* __restrict__ pts,
    int n)   // n = number of points
{
    int t = blockIdx.x * blockDim.x + threadIdx.x;   // handles points 2t, 2t+1
    int i0 = 2 * t;
    if (i0 >= n) return;

    // Camera (uniform broadcast loads)
    float R00 = __ldg(cam + 0),  R01 = __ldg(cam + 1),  R02 = __ldg(cam + 2),  t0 = __ldg(cam + 3);
    float R10 = __ldg(cam + 4),  R11 = __ldg(cam + 5),  R12 = __ldg(cam + 6),  t1 = __ldg(cam + 7);
    float R20 = __ldg(cam + 8),  R21 = __ldg(cam + 9),  R22 = __ldg(cam + 10), t2 = __ldg(cam + 11);
    float fx  = __ldg(cam + 12), fy  = __ldg(cam + 13), cx  = __ldg(cam + 14), cy = __ldg(cam + 15);

    // Two points = 48 bytes = 3 x float4, 16B-aligned (48*t bytes).
    const float4* p4 = reinterpret_cast<const float4*>(pts + (size_t)t * 12);
    float4 A = __ldcs(p4 + 0);   // x0 y0 z0 f00
    float4 B = __ldcs(p4 + 1);   // f01 f02 x1 y1
    float4 C = __ldcs(p4 + 2);   // z1 f10 f11 f12

    #pragma unroll
    for (int k = 0; k < 2; k++) {
        float px, py, pz, f0, f1, f2;
        if (k == 0) { px = A.x; py = A.y; pz = A.z; f0 = A.w; f1 = B.x; f2 = B.y; }
        else        { px = B.z; py = B.w; pz = C.x; f0 = C.y; f1 = C.z; f2 = C.w; }
        if (i0 + k >= n) break;

        // Reference-identical rounding: no FMA contraction (floor(u) boundaries).
        float xc = __fadd_rn(__fadd_rn(__fadd_rn(__fmul_rn(px, R00), __fmul_rn(py, R01)), __fmul_rn(pz, R02)), t0);
        float yc = __fadd_rn(__fadd_rn(__fadd_rn(__fmul_rn(px, R10), __fmul_rn(py, R11)), __fmul_rn(pz, R12)), t1);
        float zc = __fadd_rn(__fadd_rn(__fadd_rn(__fmul_rn(px, R20), __fmul_rn(py, R21)), __fmul_rn(pz, R22)), t2);

        float inv_z = __fdiv_rn(1.0f, fmaxf(zc, EPS_F));
        float u = __fadd_rn(__fmul_rn(__fmul_rn(fx, xc), inv_z), cx);
        float v = __fadd_rn(__fmul_rn(__fmul_rn(fy, yc), inv_z), cy);
        int ui = (int)floorf(u);
        int vi = (int)floorf(v);

        if (zc > EPS_F && ui >= 0 && ui < IMG_W && vi >= 0 && vi < IMG_H) {
            float w = inv_z;
            float4* dst = &g_accum[vi * IMG_W + ui];
            asm volatile("red.global.add.v4.f32 [%0], {%1, %2, %3, %4};"
                         :: "l"(dst),
                            "f"(__fmul_rn(w, f0)),
                            "f"(__fmul_rn(w, f1)),
                            "f"(__fmul_rn(w, f2)),
                            "f"(w)
                         : "memory");
        }
    }
}

// 4 pixels per thread: 12 env floats = 3 float4, 12 out floats = 3 float4.
// Also zeroes g_accum for the next replay.
__global__ __launch_bounds__(256) void normalize_kernel(
    const float* __restrict__ env,
    float* __restrict__ out)
{
    int t = blockIdx.x * blockDim.x + threadIdx.x;   // pixel group [4t, 4t+4)
    if (t >= NPIX / 4) return;
    int p = 4 * t;

    float4 acc0 = g_accum[p + 0];
    float4 acc1 = g_accum[p + 1];
    float4 acc2 = g_accum[p + 2];
    float4 acc3 = g_accum[p + 3];

    const float4* e4 = reinterpret_cast<const float4*>(env + (size_t)p * 3);
    float4 E0 = __ldcs(e4 + 0);   // p0.r p0.g p0.b p1.r
    float4 E1 = __ldcs(e4 + 1);   // p1.g p1.b p2.r p2.g
    float4 E2 = __ldcs(e4 + 2);   // p2.b p3.r p3.g p3.b

    float in0 = __fdiv_rn(1.0f, __fadd_rn(acc0.w, BG_WF));
    float in1 = __fdiv_rn(1.0f, __fadd_rn(acc1.w, BG_WF));
    float in2 = __fdiv_rn(1.0f, __fadd_rn(acc2.w, BG_WF));
    float in3 = __fdiv_rn(1.0f, __fadd_rn(acc3.w, BG_WF));

    float4 O0, O1, O2;
    O0.x = __fmul_rn(__fadd_rn(acc0.x, __fmul_rn(BG_WF, E0.x)), in0);
    O0.y = __fmul_rn(__fadd_rn(acc0.y, __fmul_rn(BG_WF, E0.y)), in0);
    O0.z = __fmul_rn(__fadd_rn(acc0.z, __fmul_rn(BG_WF, E0.z)), in0);
    O0.w = __fmul_rn(__fadd_rn(acc1.x, __fmul_rn(BG_WF, E0.w)), in1);
    O1.x = __fmul_rn(__fadd_rn(acc1.y, __fmul_rn(BG_WF, E1.x)), in1);
    O1.y = __fmul_rn(__fadd_rn(acc1.z, __fmul_rn(BG_WF, E1.y)), in1);
    O1.z = __fmul_rn(__fadd_rn(acc2.x, __fmul_rn(BG_WF, E1.z)), in2);
    O1.w = __fmul_rn(__fadd_rn(acc2.y, __fmul_rn(BG_WF, E1.w)), in2);
    O2.x = __fmul_rn(__fadd_rn(acc2.z, __fmul_rn(BG_WF, E2.x)), in2);
    O2.y = __fmul_rn(__fadd_rn(acc3.x, __fmul_rn(BG_WF, E2.y)), in3);
    O2.z = __fmul_rn(__fadd_rn(acc3.y, __fmul_rn(BG_WF, E2.z)), in3);
    O2.w = __fmul_rn(__fadd_rn(acc3.z, __fmul_rn(BG_WF, E2.w)), in3);

    float4* o4 = reinterpret_cast<float4*>(out + (size_t)p * 3);
    o4[0] = O0;
    o4[1] = O1;
    o4[2] = O2;

    // Re-zero accumulator for the next graph replay.
    float4 z = make_float4(0.f, 0.f, 0.f, 0.f);
    g_accum[p + 0] = z;
    g_accum[p + 1] = z;
    g_accum[p + 2] = z;
    g_accum[p + 3] = z;
}

extern "C" void kernel_launch(void* const* d_in, const int* in_sizes, int n_in,
                              void* d_out, int out_size)
{
    // Inputs: cam_type (int32), camera (16 f32), points (N*6 f32), environment (H*W*3 f32).
    const float* camera = (const float*)d_in[1];
    const float* points = (const float*)d_in[2];
    const float* env    = (const float*)d_in[3];
    float* out = (float*)d_out;
    int n = in_sizes[2] / 6;

    const int T = 256;
    int pair_threads = (n + 1) / 2;
    scatter_kernel<<<(pair_threads + T - 1) / T, T>>>(camera, points, n);
    normalize_kernel<<<(NPIX / 4 + T - 1) / T, T>>>(env, out);
}